// round 3
// baseline (speedup 1.0000x reference)
#include <cuda_runtime.h>

// YOLO head decode: x[32, 3*85, 80, 80] fp32 -> out[32, 3*80*80, 85] fp32
//   c=0: (sigmoid(v) + grid_x) * 640^2
//   c=1: (sigmoid(v) + grid_y) * 640^2
//   c=2: exp(v) * anchor_w[a] * 640^2
//   c=3: exp(v) * anchor_h[a] * 640^2
//   c>=4: sigmoid(v)
//
// Shared-memory transpose tile: 64 contiguous spatial locations x 85 channels.
// Phase 1: coalesced channel-row loads + transform -> smem[s*85+c] (stride 85,
//          gcd(85,32)=1 -> conflict-free).
// Phase 2: linear float4 copy of the contiguous 5440-float output chunk.

#define NBATCH   32
#define NANCH    3
#define NCH      85            // C+5
#define SPATIAL  6400          // 80*80
#define GW       80
#define TILE     64            // spatial locations per block
#define NTILES   (SPATIAL / TILE)   // 100
#define THREADS  256
#define ELEMS    (TILE * NCH)       // 5440
#define SCALE    409600.0f          // 640*640

__global__ __launch_bounds__(THREADS)
void yolo_decode_kernel(const float* __restrict__ in, float* __restrict__ out)
{
    __shared__ float sm[ELEMS];   // 21.76 KB

    const int bt   = blockIdx.x;
    const int tile = bt % NTILES;
    const int na   = bt / NTILES;      // 0..95
    const int n    = na / NANCH;
    const int a    = na - n * NANCH;

    const float aw = (a == 0) ? 10.0f : (a == 1) ? 16.0f : 33.0f;
    const float ah = (a == 0) ? 13.0f : (a == 1) ? 30.0f : 23.0f;

    const int s_base   = tile * TILE;
    // input: element (n, a*85+c, s) at (n*255 + a*85 + c)*6400 + s
    const int base_in  = (n * (NANCH * NCH) + a * NCH) * SPATIAL + s_base;
    // output: element (n, a*6400+s, c) at ((n*19200 + a*6400 + s)*85 + c)
    const int base_out = (n * (NANCH * SPATIAL) + a * SPATIAL + s_base) * NCH;

    // ---- Phase 1: load (coalesced per channel row), transform, transpose into smem
    for (int idx = threadIdx.x; idx < ELEMS; idx += THREADS) {
        const int c  = idx / TILE;      // channel 0..84
        const int s0 = idx - c * TILE;  // 0..63
        const float v = in[base_in + c * SPATIAL + s0];

        float r;
        if (c >= 4) {
            // obj / class confidences: plain sigmoid
            r = __fdividef(1.0f, 1.0f + __expf(-v));
        } else {
            const int sabs = s_base + s0;
            if (c == 0) {
                const float gx = (float)(sabs % GW);
                r = (__fdividef(1.0f, 1.0f + __expf(-v)) + gx) * SCALE;
            } else if (c == 1) {
                const float gy = (float)(sabs / GW);
                r = (__fdividef(1.0f, 1.0f + __expf(-v)) + gy) * SCALE;
            } else if (c == 2) {
                r = __expf(v) * (aw * SCALE);
            } else { // c == 3
                r = __expf(v) * (ah * SCALE);
            }
        }
        sm[s0 * NCH + c] = r;
    }

    __syncthreads();

    // ---- Phase 2: contiguous float4 store of the whole tile's output chunk.
    // base_out is a multiple of 5440 (tile-aligned) -> 16B aligned.
    const float4* __restrict__ sm4  = reinterpret_cast<const float4*>(sm);
    float4*       __restrict__ out4 = reinterpret_cast<float4*>(out + base_out);
    #pragma unroll 4
    for (int idx = threadIdx.x; idx < ELEMS / 4; idx += THREADS) {
        out4[idx] = sm4[idx];
    }
}

extern "C" void kernel_launch(void* const* d_in, const int* in_sizes, int n_in,
                              void* d_out, int out_size)
{
    const float* x   = (const float*)d_in[0];
    float*       out = (float*)d_out;
    (void)in_sizes; (void)n_in; (void)out_size;

    const int grid = NBATCH * NANCH * NTILES;   // 32*3*100 = 9600
    yolo_decode_kernel<<<grid, THREADS>>>(x, out);
}

// round 4
// speedup vs baseline: 1.9589x; 1.9589x over previous
#include <cuda_runtime.h>

// YOLO head decode: x[32, 3*85, 80, 80] fp32 -> out[32, 3*80*80, 85] fp32
//   c=0: (sigmoid(v) + grid_x) * 640^2
//   c=1: (sigmoid(v) + grid_y) * 640^2
//   c=2: exp(v) * anchor_w[a] * 640^2
//   c=3: exp(v) * anchor_h[a] * 640^2
//   c>=4: sigmoid(v)
//
// R4: explicit-MLP phase 1. Each thread front-loads up to 6 independent
// LDG.128s (float4) before any transform -> MLP ~6 instead of ~1 (regs=25
// in R3 meant ptxas couldn't batch; DRAM stuck at 35.7%).
// sigmoid via tanh.approx (1 special op instead of EX2+RCP).

#define NBATCH   32
#define NANCH    3
#define NCH      85                  // C+5
#define SPATIAL  6400                // 80*80
#define GW       80
#define TILE     64                  // spatial locations per block
#define NTILES   (SPATIAL / TILE)    // 100
#define THREADS  256
#define ELEMS    (TILE * NCH)        // 5440 floats
#define ELEMS4   (ELEMS / 4)         // 1360 float4
#define NBATCHJ  6                   // ceil(1360/256)
#define SCALE    409600.0f           // 640*640

__device__ __forceinline__ float fast_sigmoid(float x)
{
    float t;
    asm("tanh.approx.f32 %0, %1;" : "=f"(t) : "f"(0.5f * x));
    return fmaf(0.5f, t, 0.5f);
}

__global__ __launch_bounds__(THREADS)
void yolo_decode_kernel(const float* __restrict__ in, float* __restrict__ out)
{
    __shared__ float sm[ELEMS];   // 21.76 KB

    const int bt   = blockIdx.x;
    const int tile = bt % NTILES;
    const int na   = bt / NTILES;      // 0..95
    const int n    = na / NANCH;
    const int a    = na - n * NANCH;

    const float awS = ((a == 0) ? 10.0f : (a == 1) ? 16.0f : 33.0f) * SCALE;
    const float ahS = ((a == 0) ? 13.0f : (a == 1) ? 30.0f : 23.0f) * SCALE;

    const int s_base   = tile * TILE;
    // input elem (n, a*85+c, s): (n*255 + a*85 + c)*6400 + s
    const int base_in  = (n * (NANCH * NCH) + a * NCH) * SPATIAL + s_base;
    // output elem (n, a*6400+s, c): (n*19200 + a*6400 + s)*85 + c
    const int base_out = (n * (NANCH * SPATIAL) + a * SPATIAL + s_base) * NCH;

    const float4* __restrict__ in4 = reinterpret_cast<const float4*>(in);
    const int base4 = base_in >> 2;    // base_in is a multiple of 4

    // ---- Phase 1a: front-batch up to 6 independent LDG.128 per thread.
    // float4 index q in [0,1360): c = q>>4 (channel), sq = q&15 (quad within
    // the 64-float channel row). Per-q address: base4 + c*1600 + sq.
    float4 v[NBATCHJ];
    #pragma unroll
    for (int j = 0; j < NBATCHJ; j++) {
        const int q = threadIdx.x + j * THREADS;
        if (q < ELEMS4) {
            const int c  = q >> 4;
            const int sq = q & 15;
            v[j] = in4[base4 + c * (SPATIAL / 4) + sq];
        }
    }

    // ---- Phase 1b: transform + transposed STS (sm[s0*85 + c]).
    #pragma unroll
    for (int j = 0; j < NBATCHJ; j++) {
        const int q = threadIdx.x + j * THREADS;
        if (q < ELEMS4) {
            const int c  = q >> 4;
            const int sq = q & 15;
            const int s0 = sq << 2;
            const float vv[4] = { v[j].x, v[j].y, v[j].z, v[j].w };
            #pragma unroll
            for (int k = 0; k < 4; k++) {
                const float x = vv[k];
                float r;
                if (c >= 4) {
                    r = fast_sigmoid(x);
                } else if (c == 0) {
                    const int sabs = s_base + s0 + k;
                    r = (fast_sigmoid(x) + (float)(sabs % GW)) * SCALE;
                } else if (c == 1) {
                    const int sabs = s_base + s0 + k;
                    r = (fast_sigmoid(x) + (float)(sabs / GW)) * SCALE;
                } else if (c == 2) {
                    r = __expf(x) * awS;
                } else { // c == 3
                    r = __expf(x) * ahS;
                }
                sm[(s0 + k) * NCH + c] = r;
            }
        }
    }

    __syncthreads();

    // ---- Phase 2: contiguous float4 store of the tile's 5440-float chunk.
    const float4* __restrict__ sm4  = reinterpret_cast<const float4*>(sm);
    float4*       __restrict__ out4 = reinterpret_cast<float4*>(out + base_out);
    #pragma unroll
    for (int j = 0; j < NBATCHJ; j++) {
        const int q = threadIdx.x + j * THREADS;
        if (q < ELEMS4) out4[q] = sm4[q];
    }
}

extern "C" void kernel_launch(void* const* d_in, const int* in_sizes, int n_in,
                              void* d_out, int out_size)
{
    const float* x   = (const float*)d_in[0];
    float*       out = (float*)d_out;
    (void)in_sizes; (void)n_in; (void)out_size;

    const int grid = NBATCH * NANCH * NTILES;   // 9600
    yolo_decode_kernel<<<grid, THREADS>>>(x, out);
}

// round 5
// speedup vs baseline: 1.9655x; 1.0034x over previous
#include <cuda_runtime.h>
#include <cstdint>

// YOLO head decode: x[32, 3*85, 80, 80] fp32 -> out[32, 3*80*80, 85] fp32
//   c=0: (sigmoid(v) + grid_x) * 640^2      c=1: (sigmoid(v) + grid_y) * 640^2
//   c=2: exp(v) * anchor_w[a] * 640^2       c=3: exp(v) * anchor_h[a] * 640^2
//   c>=4: sigmoid(v)
//
// R5: phase-2 smem->gmem copy replaced by ONE cp.async.bulk (TMA bulk store)
// per CTA. The 5440-float output chunk is contiguous and 16B-aligned, so the
// TMA engine does the write while the SM's warps retire -> L1/issue freed,
// next-wave LDGs start earlier. Phase 1 keeps the R4 explicit-MLP batch
// (6 independent LDG.128 per thread).

#define NBATCH   32
#define NANCH    3
#define NCH      85                  // C+5
#define SPATIAL  6400                // 80*80
#define GW       80
#define TILE     64                  // spatial locations per block
#define NTILES   (SPATIAL / TILE)    // 100
#define THREADS  256
#define ELEMS    (TILE * NCH)        // 5440 floats
#define ELEMS4   (ELEMS / 4)         // 1360 float4
#define NBATCHJ  6                   // ceil(1360/256)
#define SCALE    409600.0f           // 640*640

__device__ __forceinline__ float fast_sigmoid(float x)
{
    float t;
    asm("tanh.approx.f32 %0, %1;" : "=f"(t) : "f"(0.5f * x));
    return fmaf(0.5f, t, 0.5f);
}

__global__ __launch_bounds__(THREADS)
void yolo_decode_kernel(const float* __restrict__ in, float* __restrict__ out)
{
    __shared__ __align__(128) float sm[ELEMS];   // 21.76 KB

    const int bt   = blockIdx.x;
    const int tile = bt % NTILES;
    const int na   = bt / NTILES;      // 0..95
    const int n    = na / NANCH;
    const int a    = na - n * NANCH;

    const float awS = ((a == 0) ? 10.0f : (a == 1) ? 16.0f : 33.0f) * SCALE;
    const float ahS = ((a == 0) ? 13.0f : (a == 1) ? 30.0f : 23.0f) * SCALE;

    const int s_base   = tile * TILE;
    // input elem (n, a*85+c, s): (n*255 + a*85 + c)*6400 + s
    const int base_in  = (n * (NANCH * NCH) + a * NCH) * SPATIAL + s_base;
    // output elem (n, a*6400+s, c): (n*19200 + a*6400 + s)*85 + c
    const int base_out = (n * (NANCH * SPATIAL) + a * SPATIAL + s_base) * NCH;

    const float4* __restrict__ in4 = reinterpret_cast<const float4*>(in);
    const int base4 = base_in >> 2;    // base_in is a multiple of 4

    // ---- Phase 1a: front-batch up to 6 independent LDG.128 per thread.
    // float4 index q in [0,1360): c = q>>4, sq = q&15 (quad within the
    // 64-float channel row). Address: base4 + c*1600 + sq.
    float4 v[NBATCHJ];
    #pragma unroll
    for (int j = 0; j < NBATCHJ; j++) {
        const int q = threadIdx.x + j * THREADS;
        if (q < ELEMS4) {
            const int c  = q >> 4;
            const int sq = q & 15;
            v[j] = in4[base4 + c * (SPATIAL / 4) + sq];
        }
    }

    // ---- Phase 1b: transform + transposed STS (sm[s0*85 + c]).
    #pragma unroll
    for (int j = 0; j < NBATCHJ; j++) {
        const int q = threadIdx.x + j * THREADS;
        if (q < ELEMS4) {
            const int c  = q >> 4;
            const int sq = q & 15;
            const int s0 = sq << 2;
            const float vv[4] = { v[j].x, v[j].y, v[j].z, v[j].w };
            #pragma unroll
            for (int k = 0; k < 4; k++) {
                const float x = vv[k];
                float r;
                if (c >= 4) {
                    r = fast_sigmoid(x);
                } else if (c == 0) {
                    const int sabs = s_base + s0 + k;
                    r = (fast_sigmoid(x) + (float)(sabs % GW)) * SCALE;
                } else if (c == 1) {
                    const int sabs = s_base + s0 + k;
                    r = (fast_sigmoid(x) + (float)(sabs / GW)) * SCALE;
                } else if (c == 2) {
                    r = __expf(x) * awS;
                } else { // c == 3
                    r = __expf(x) * ahS;
                }
                sm[(s0 + k) * NCH + c] = r;
            }
        }
    }

    __syncthreads();

    // ---- Phase 2: single TMA bulk store of the contiguous 21760-byte chunk.
    if (threadIdx.x == 0) {
        uint32_t smem_addr;
        asm("{ .reg .u64 t; cvta.to.shared.u64 t, %1; cvt.u32.u64 %0, t; }"
            : "=r"(smem_addr) : "l"((const void*)sm));
        // Generic-proxy STS results must be visible to the async proxy.
        asm volatile("fence.proxy.async.shared::cta;" ::: "memory");
        asm volatile(
            "cp.async.bulk.global.shared::cta.bulk_group [%0], [%1], %2;"
            :: "l"(out + base_out), "r"(smem_addr), "r"((int)(ELEMS * 4))
            : "memory");
        asm volatile("cp.async.bulk.commit_group;" ::: "memory");
        // Must drain before CTA exit: next CTA on this SM reuses the smem.
        asm volatile("cp.async.bulk.wait_group 0;" ::: "memory");
    }
}

extern "C" void kernel_launch(void* const* d_in, const int* in_sizes, int n_in,
                              void* d_out, int out_size)
{
    const float* x   = (const float*)d_in[0];
    float*       out = (float*)d_out;
    (void)in_sizes; (void)n_in; (void)out_size;

    const int grid = NBATCH * NANCH * NTILES;   // 9600
    yolo_decode_kernel<<<grid, THREADS>>>(x, out);
}